// round 1
// baseline (speedup 1.0000x reference)
#include <cuda_runtime.h>
#include <cstdint>

#define NB 2
#define NV 1024
#define NF 2048
#define NC 3
#define NH 128
#define NW 128
#define SEG 8
#define CHK (NF / SEG)   // 256 faces per raster block

#define FTINY  ((float)1.1754943508222875e-35)            // finfo(f32).tiny * 1000
#define FINF   ((float)(3.4028234663852886e38 * 0.001))   // finfo(f32).max * 0.001
#define FLOWER ((float)(3.4028234663852886e38 * 0.0001))  // finfo(f32).max * 0.0001

// Scratch (no allocations allowed): per-face coefficients + per-pixel argmin keys
__device__ float g_face[NB * NF * 16];
__device__ unsigned long long g_scr[NB * NH * NW];

// ---- exact-rounding helpers (match XLA's non-contracted mul/add) ----
__device__ __forceinline__ float f_mul(float a, float b) { return __fmul_rn(a, b); }
__device__ __forceinline__ float f_add(float a, float b) { return __fadd_rn(a, b); }
__device__ __forceinline__ float f_sub(float a, float b) { return __fsub_rn(a, b); }
// (a*x + b*y) + c  with left association, no FMA contraction
__device__ __forceinline__ float plane3(float a, float x, float b, float y, float c) {
    return f_add(f_add(f_mul(a, x), f_mul(b, y)), c);
}

// Orderable key for fp32 (monotonic over all non-NaN floats)
__device__ __forceinline__ unsigned int fkey(float f) {
    unsigned int u = __float_as_uint(f);
    return (u & 0x80000000u) ? ~u : (u | 0x80000000u);
}
__device__ __forceinline__ float fkey_inv(unsigned int k) {
    unsigned int u = (k & 0x80000000u) ? (k ^ 0x80000000u) : ~k;
    return __uint_as_float(u);
}

// Barycentric plane coefficients — exact replication of _bary_coeffs
__device__ __forceinline__ void bary_coeffs(
    float x0, float x1, float x2, float y0, float y1, float y2,
    float& l0x, float& l0y, float& l0c,
    float& l1x, float& l1y, float& l1c,
    float& l2x, float& l2y, float& l2c)
{
    float det = f_add(f_mul(f_sub(y1, y2), f_sub(x0, x2)),
                      f_mul(f_sub(x2, x1), f_sub(y0, y2)));
    float s  = (det > 0.0f) ? 1.0f : ((det < 0.0f) ? -1.0f : 0.0f);
    float dd = f_mul(s, fmaxf(fabsf(det), FTINY));
    float inv = __fdiv_rn(1.0f, dd);
    l0x = f_mul(f_sub(y1, y2), inv);
    l0y = f_mul(f_sub(x2, x1), inv);
    l0c = f_sub(f_mul(-l0x, x2), f_mul(l0y, y2));
    l1x = f_mul(f_sub(y2, y0), inv);
    l1y = f_mul(f_sub(x0, x2), inv);
    l1c = f_sub(f_mul(-l1x, x2), f_mul(l1y, y2));
    l2x = f_sub(-l0x, l1x);
    l2y = f_sub(-l0y, l1y);
    l2c = f_sub(f_sub(1.0f, l0c), l1c);
}

// ---- K0: init per-pixel keys to (INF, face 0) ----
__global__ void k_init() {
    int id = blockIdx.x * blockDim.x + threadIdx.x;
    if (id < NB * NH * NW)
        g_scr[id] = ((unsigned long long)fkey(FINF)) << 32;  // idx = 0
}

// ---- K1: per-face setup ----
__global__ void k_setup(const float* __restrict__ pt2d, const float* __restrict__ pt3d,
                        const float* __restrict__ normal, const float* __restrict__ Rm,
                        const float* __restrict__ Tm, const int* __restrict__ face)
{
    int id = blockIdx.x * blockDim.x + threadIdx.x;
    if (id >= NB * NF) return;
    int b = id / NF, f = id % NF;

    int i0 = face[f], i1 = face[NF + f], i2 = face[2 * NF + f];
    const float* p2 = pt2d + b * 3 * NV;
    float x0 = p2[i0],          x1 = p2[i1],          x2 = p2[i2];
    float y0 = p2[NV + i0],     y1 = p2[NV + i1],     y2 = p2[NV + i2];
    float z0 = p2[2 * NV + i0], z1 = p2[2 * NV + i1], z2 = p2[2 * NV + i2];

    // norm cull: ((v0 + R^T T) . n) < 0
    const float* p3 = pt3d + b * 3 * NV;
    float v0x = p3[i0], v0y = p3[NV + i0], v0z = p3[2 * NV + i0];
    const float* nb = normal + b * 3 * NF;
    float nx = nb[f], ny = nb[NF + f], nz = nb[2 * NF + f];
    const float* R = Rm + b * 9;
    const float* T = Tm + b * 3;
    float o0 = f_add(f_add(f_mul(R[0], T[0]), f_mul(R[3], T[1])), f_mul(R[6], T[2]));
    float o1 = f_add(f_add(f_mul(R[1], T[0]), f_mul(R[4], T[1])), f_mul(R[7], T[2]));
    float o2 = f_add(f_add(f_mul(R[2], T[0]), f_mul(R[5], T[1])), f_mul(R[8], T[2]));
    float dotv = f_add(f_add(f_mul(f_add(v0x, o0), nx),
                             f_mul(f_add(v0y, o1), ny)),
                       f_mul(f_add(v0z, o2), nz));
    bool norm_cul  = dotv < 0.0f;
    bool depth_cul = fminf(z0, fminf(z1, z2)) > 0.0f;
    bool valid = norm_cul && depth_cul;

    float l0x, l0y, l0c, l1x, l1y, l1c, l2x, l2y, l2c;
    bary_coeffs(x0, x1, x2, y0, y1, y2, l0x, l0y, l0c, l1x, l1y, l1c, l2x, l2y, l2c);

    float Dx = f_add(f_add(f_mul(z0, l0x), f_mul(z1, l1x)), f_mul(z2, l2x));
    float Dy = f_add(f_add(f_mul(z0, l0y), f_mul(z1, l1y)), f_mul(z2, l2y));
    float Dc = f_add(f_add(f_mul(z0, l0c), f_mul(z1, l1c)), f_mul(z2, l2c));

    float xmin = fminf(x0, fminf(x1, x2)), xmax = fmaxf(x0, fmaxf(x1, x2));
    float ymin = fminf(y0, fminf(y1, y2)), ymax = fmaxf(y0, fmaxf(y1, y2));
    if (!valid) xmin = 3e38f;  // fold validity into bbox: test always fails

    float4* o4 = (float4*)(g_face + id * 16);
    o4[0] = make_float4(l0x, l0y, l0c, l1x);
    o4[1] = make_float4(l1y, l1c, l2x, l2y);
    o4[2] = make_float4(l2c, Dx,  Dy,  Dc);
    o4[3] = make_float4(xmin, ymin, xmax, ymax);
}

// ---- K2: rasterize (argmin of depth over a face segment, per pixel) ----
// Block = 256 threads = 16x16 lattice; each thread owns 2 pixels (y, y+16).
// Grid = (W/16, H/32, NB*SEG). Face segment staged through shared memory.
__global__ void __launch_bounds__(256) k_raster() {
    __shared__ float4 sm[CHK * 4];   // 16 KB

    int bz  = blockIdx.z;
    int b   = bz / SEG;
    int seg = bz % SEG;
    int tid = threadIdx.x;

    const float4* g = (const float4*)(g_face + (b * NF + seg * CHK) * 16);
    for (int i = tid; i < CHK * 4; i += 256) sm[i] = g[i];
    __syncthreads();

    int x     = blockIdx.x * 16 + (tid & 15);
    int ybase = blockIdx.y * 32 + (tid >> 4);
    float xf  = (float)x;
    float yf0 = (float)ybase;
    float yf1 = (float)(ybase + 16);

    const unsigned long long INIT = 0xFFFFFFFFFFFFFFFFull;
    unsigned long long best0 = INIT, best1 = INIT;
    int fbase = seg * CHK;

    for (int f = 0; f < CHK; f++) {
        float4 Dq = sm[f * 4 + 3];
        if (Dq.x > 1e37f) continue;          // invalid (culled) face
        float4 A  = sm[f * 4 + 0];           // l0x,l0y,l0c,l1x
        float4 Bq = sm[f * 4 + 1];           // l1y,l1c,l2x,l2y
        float4 Cq = sm[f * 4 + 2];           // l2c,Dx, Dy, Dc
        unsigned long long fi = (unsigned long long)(fbase + f);

        {   // pixel (x, ybase)
            float l0 = plane3(A.x,  xf, A.y,  yf0, A.z);
            float l1 = plane3(A.w,  xf, Bq.x, yf0, Bq.y);
            float l2 = plane3(Bq.z, xf, Bq.w, yf0, Cq.x);
            if (l0 >= 0.0f && l1 >= 0.0f && l2 >= 0.0f) {
                float d = plane3(Cq.y, xf, Cq.z, yf0, Cq.w);
                if (d == d) {  // NaN -> treated as INF (never wins)
                    unsigned long long k = (((unsigned long long)fkey(d)) << 32) | fi;
                    best0 = min(best0, k);
                }
            }
        }
        {   // pixel (x, ybase+16)
            float l0 = plane3(A.x,  xf, A.y,  yf1, A.z);
            float l1 = plane3(A.w,  xf, Bq.x, yf1, Bq.y);
            float l2 = plane3(Bq.z, xf, Bq.w, yf1, Cq.x);
            if (l0 >= 0.0f && l1 >= 0.0f && l2 >= 0.0f) {
                float d = plane3(Cq.y, xf, Cq.z, yf1, Cq.w);
                if (d == d) {
                    unsigned long long k = (((unsigned long long)fkey(d)) << 32) | fi;
                    best1 = min(best1, k);
                }
            }
        }
    }

    if (best0 != INIT) atomicMin(&g_scr[b * NH * NW + ybase * NW + x], best0);
    if (best1 != INIT) atomicMin(&g_scr[b * NH * NW + (ybase + 16) * NW + x], best1);
}

// ---- K3: shade ----
__global__ void k_shade(const float* __restrict__ pt2d, const float* __restrict__ color,
                        const int* __restrict__ face, float* __restrict__ out)
{
    int id = blockIdx.x * blockDim.x + threadIdx.x;
    if (id >= NB * NH * NW) return;
    int b   = id / (NH * NW);
    int rem = id % (NH * NW);
    int y = rem / NW, x = rem % NW;

    unsigned long long key = g_scr[id];
    int idx = (int)(key & 0xFFFFFFFFull);
    float depth = fkey_inv((unsigned int)(key >> 32));
    float mask = (depth < FLOWER) ? 1.0f : 0.0f;

    int i0 = face[idx], i1 = face[NF + idx], i2 = face[2 * NF + idx];
    const float* p2 = pt2d + b * 3 * NV;
    float x0 = p2[i0],      x1 = p2[i1],      x2 = p2[i2];
    float y0 = p2[NV + i0], y1 = p2[NV + i1], y2 = p2[NV + i2];

    float l0x, l0y, l0c, l1x, l1y, l1c, l2x, l2y, l2c;
    bary_coeffs(x0, x1, x2, y0, y1, y2, l0x, l0y, l0c, l1x, l1y, l1c, l2x, l2y, l2c);

    float xf = (float)x, yf = (float)y;
    const float* cb = color + b * 3 * NV;
    #pragma unroll
    for (int ch = 0; ch < NC; ch++) {
        float c0 = cb[ch * NV + i0], c1 = cb[ch * NV + i1], c2 = cb[ch * NV + i2];
        float Cx = f_add(f_add(f_mul(c0, l0x), f_mul(c1, l1x)), f_mul(c2, l2x));
        float Cy = f_add(f_add(f_mul(c0, l0y), f_mul(c1, l1y)), f_mul(c2, l2y));
        float Cc = f_add(f_add(f_mul(c0, l0c), f_mul(c1, l1c)), f_mul(c2, l2c));
        float val = f_add(f_add(f_mul(Cx, xf), f_mul(Cy, yf)), Cc);
        out[((b * NC + ch) * NH + y) * NW + x] = f_mul(mask, val);
    }
    out[NB * NC * NH * NW + id] = mask;
}

extern "C" void kernel_launch(void* const* d_in, const int* in_sizes, int n_in,
                              void* d_out, int out_size)
{
    const float* pt2d   = (const float*)d_in[0];
    const float* color  = (const float*)d_in[1];
    const float* pt3d   = (const float*)d_in[2];
    const float* normal = (const float*)d_in[3];
    const float* Rm     = (const float*)d_in[4];
    const float* Tm     = (const float*)d_in[5];
    const int*   face   = (const int*)d_in[6];
    float* out = (float*)d_out;

    k_init<<<(NB * NH * NW) / 256, 256>>>();
    k_setup<<<(NB * NF) / 256, 256>>>(pt2d, pt3d, normal, Rm, Tm, face);
    dim3 g2(NW / 16, NH / 32, NB * SEG);
    k_raster<<<g2, 256>>>();
    k_shade<<<(NB * NH * NW) / 256, 256>>>(pt2d, color, face, out);
}